// round 14
// baseline (speedup 1.0000x reference)
#include <cuda_runtime.h>
#include <cuda_fp16.h>

#define GRID 144
#define NT   640          // 20 warps

typedef unsigned u32;

// ---- global scratch ----
__device__ float g_part[(size_t)GRID * 128 * 160];   // [blk][b][jd] partials
__device__ unsigned short g_vh[160 * 128];           // v fp16 [jd][b]
__device__ unsigned g_cnt = 0;
__device__ volatile unsigned g_gen = 0;

// ---- smem byte offsets ----
#define O_WH  0           // W hi  [160 jd][36 u32(rc pairs, permuted)]
#define O_WL  23040
#define O_PH  46080       // W' hi (c*W)
#define O_PL  69120
#define O_XH  92160       // X hi  [128 b][36 u32 permuted]
#define O_XL  110592
#define O_XTH 129024      // XT hi [64 rc][136 halves(b)]
#define O_XTL 146432
#define O_V   163840      // V fp16 [160 jd][68 u32(b pairs)]
#define O_SB  207360      // float[80] b_ij
#define O_SD  207680      // float[80] delta
#define O_SC  208000      // float[80] c
#define O_SRD 208320      // float[2304] reduce scratch
#define SMEM_BYTES 217536

// permutation: u32-pair index p (0..31) -> q so fragment pairs (p, p+4) adjacent
__device__ __forceinline__ int permq(int p) {
    return (p & 24) | ((p & 3) << 1) | ((p >> 2) & 1);
}

// ---- fp16 mma m16n8k16, D += A*B ----
__device__ __forceinline__ void mma16(float* c, u32 a0, u32 a1, u32 a2, u32 a3,
                                      u32 b0, u32 b1) {
    asm volatile(
        "mma.sync.aligned.m16n8k16.row.col.f32.f16.f16.f32 "
        "{%0,%1,%2,%3},{%4,%5,%6,%7},{%8,%9},{%0,%1,%2,%3};"
        : "+f"(c[0]), "+f"(c[1]), "+f"(c[2]), "+f"(c[3])
        : "r"(a0), "r"(a1), "r"(a2), "r"(a3), "r"(b0), "r"(b1));
}
__device__ __forceinline__ float2 h2f2(u32 h) {
    return __half22float2(*(const __half2*)&h);
}

// ---- one-wave grid barrier ----
__device__ __forceinline__ void grid_sync(int t) {
    __syncthreads();
    if (t == 0) {
        __threadfence();
        unsigned gen = g_gen;
        if (atomicAdd(&g_cnt, 1u) == GRID - 1) {
            atomicExch(&g_cnt, 0u);
            __threadfence();
            g_gen = gen + 1;
        } else {
            while (g_gen == gen) { __nanosleep(32); }
        }
        __threadfence();
    }
    __syncthreads();
}

// ---------------------------------------------------------------------------
// s-GEMM: partial s[b,jd] = scale * sum_rc X[b,rc]*A[jd,rc]   (A = W or c∘W)
// 20 warps: warp = (mb in [0,4) b-tile of 32, nq in [0,5) jd-tile of 32)
// per warp: 2 m-subtiles x 4 n-tiles x 4 kt x 3 split = 96 MMAs, 64 LDS.64
// ---------------------------------------------------------------------------
__device__ __forceinline__ void s_gemm(char* smem, int t, int blk,
                                       int AH, int AL, float scale) {
    int lane = t & 31, w = t >> 5, gid = lane >> 2, tig = lane & 3;
    int mb = w & 3, nq = w >> 2;
    int b0 = mb * 32, jd0 = nq * 32;
    const u32* xh_ = (const u32*)(smem + O_XH);
    const u32* xl_ = (const u32*)(smem + O_XL);
    const u32* wh_ = (const u32*)(smem + AH);
    const u32* wl_ = (const u32*)(smem + AL);

    float acc[2][4][4];
#pragma unroll
    for (int m = 0; m < 2; m++)
#pragma unroll
        for (int n = 0; n < 4; n++)
#pragma unroll
            for (int k = 0; k < 4; k++) acc[m][n][k] = 0.f;

#pragma unroll
    for (int kt = 0; kt < 4; kt++) {
        int ko = kt * 8 + tig * 2;
        uint2 axh[2][2], axl[2][2];
#pragma unroll
        for (int ms = 0; ms < 2; ms++) {
            int rb = b0 + ms * 16 + gid;
            axh[ms][0] = *(const uint2*)(xh_ + rb * 36 + ko);
            axh[ms][1] = *(const uint2*)(xh_ + (rb + 8) * 36 + ko);
            axl[ms][0] = *(const uint2*)(xl_ + rb * 36 + ko);
            axl[ms][1] = *(const uint2*)(xl_ + (rb + 8) * 36 + ko);
        }
#pragma unroll
        for (int n = 0; n < 4; n++) {
            int rw = jd0 + n * 8 + gid;
            uint2 bh = *(const uint2*)(wh_ + rw * 36 + ko);
            uint2 bl = *(const uint2*)(wl_ + rw * 36 + ko);
#pragma unroll
            for (int ms = 0; ms < 2; ms++) {
                mma16(acc[ms][n], axh[ms][0].x, axh[ms][1].x,
                      axh[ms][0].y, axh[ms][1].y, bh.x, bh.y);
                mma16(acc[ms][n], axh[ms][0].x, axh[ms][1].x,
                      axh[ms][0].y, axh[ms][1].y, bl.x, bl.y);
                mma16(acc[ms][n], axl[ms][0].x, axl[ms][1].x,
                      axl[ms][0].y, axl[ms][1].y, bh.x, bh.y);
            }
        }
    }

    float* gp = g_part + (size_t)blk * 20480;
#pragma unroll
    for (int ms = 0; ms < 2; ms++) {
        int b = b0 + ms * 16 + gid;
#pragma unroll
        for (int n = 0; n < 4; n++) {
            int jd = jd0 + n * 8 + 2 * tig;
            __stcg((float2*)(gp + (size_t)b * 160 + jd),
                   make_float2(acc[ms][n][0] * scale, acc[ms][n][1] * scale));
            __stcg((float2*)(gp + (size_t)(b + 8) * 160 + jd),
                   make_float2(acc[ms][n][2] * scale, acc[ms][n][3] * scale));
        }
    }
}

// ---------------------------------------------------------------------------
// merged reduce + squash: all 144 blocks, 9 (j,b) columns each.
// ---------------------------------------------------------------------------
__device__ __forceinline__ void reduce_squash(char* smem, int blk, int t,
                                              float* out, int fin) {
    float*  SRD  = (float*)(smem + O_SRD);
    float4* SRD4 = (float4*)SRD;
    if (t < 576) {
        int ci = t >> 6, q = (t >> 4) & 3, ks = t & 15;
        int col = blk * 9 + ci;
        int colc = col < 1280 ? col : 1279;
        int j = colc >> 7, b = colc & 127;
        const size_t BS = 5120;   // float4 per partial block
        const float4* p = (const float4*)
            (g_part + (size_t)ks * 20480 + (size_t)b * 160 + j * 16 + q * 4);
        float4 a0 = __ldcg(p);
        float4 a1 = __ldcg(p + 16 * BS);
        float4 a2 = __ldcg(p + 32 * BS);
        float4 a3 = __ldcg(p + 48 * BS);
        float4 v0 = __ldcg(p + 64 * BS);
        float4 v1 = __ldcg(p + 80 * BS);
        float4 v2 = __ldcg(p + 96 * BS);
        float4 v3 = __ldcg(p + 112 * BS);
        float4 v4 = __ldcg(p + 128 * BS);
        a0.x += v0.x; a0.y += v0.y; a0.z += v0.z; a0.w += v0.w;
        a1.x += v1.x; a1.y += v1.y; a1.z += v1.z; a1.w += v1.w;
        a2.x += v2.x; a2.y += v2.y; a2.z += v2.z; a2.w += v2.w;
        a3.x += v3.x; a3.y += v3.y; a3.z += v3.z; a3.w += v3.w;
        a0.x += v4.x; a0.y += v4.y; a0.z += v4.z; a0.w += v4.w;
        a0.x += a1.x + a2.x + a3.x;
        a0.y += a1.y + a2.y + a3.y;
        a0.z += a1.z + a2.z + a3.z;
        a0.w += a1.w + a2.w + a3.w;
        SRD4[ci * 64 + q * 16 + ks] = a0;
    }
    __syncthreads();
    if (t < 160) {
        int ci = t >> 4, d = t & 15;
        int cir = ci < 9 ? ci : 8;
        int col = blk * 9 + ci;
        int valid = (ci < 9) && (col < 1280);
        int colc = col < 1280 ? col : 1279;
        int j = colc >> 7, b = colc & 127;
        float s = 0.f;
#pragma unroll
        for (int ks = 0; ks < 16; ks++)
            s += SRD[cir * 256 + (d >> 2) * 64 + ks * 4 + (d & 3)];
        float sq = s * s;
#pragma unroll
        for (int o = 8; o; o >>= 1) sq += __shfl_xor_sync(0xffffffffu, sq, o, 16);
        float v = s * (sqrtf(sq) / (1.f + sq));
        if (valid) {
            if (fin) out[b * 160 + j * 16 + d] = v;
            else g_vh[(j * 16 + d) * 128 + b] = __half_as_ushort(__float2half_rn(v));
        }
    }
}

// ---------------------------------------------------------------------------
// M-GEMM + delta: M[jd,rc] = sum_b V[jd,b]*X[rc,b];
// delta[r,j=mt] = sum_{d,c} W[jd,rc]*M[jd,rc]; warp = (mt, nh): 4 routes each
// ---------------------------------------------------------------------------
__device__ __forceinline__ void m_delta(char* smem, int t) {
    int lane = t & 31, w = t >> 5, gid = lane >> 2, tig = lane & 3;
    int mt = w % 10, nh = w / 10;
    const u32* v_  = (const u32*)(smem + O_V);
    const u32* bh_ = (const u32*)(smem + O_XTH);
    const u32* bl_ = (const u32*)(smem + O_XTL);
    int jr0 = (mt * 16 + gid) * 68, jr1 = (mt * 16 + gid + 8) * 68;

    float acc[4][4];
#pragma unroll
    for (int n = 0; n < 4; n++)
#pragma unroll
        for (int k = 0; k < 4; k++) acc[n][k] = 0.f;

#pragma unroll
    for (int kt = 0; kt < 8; kt++) {
        int ka = kt * 8 + tig;
        u32 a0 = v_[jr0 + ka], a1 = v_[jr1 + ka];
        u32 a2 = v_[jr0 + ka + 4], a3 = v_[jr1 + ka + 4];
#pragma unroll
        for (int n = 0; n < 4; n++) {
            int xb = ((nh * 4 + n) * 8 + gid) * 68 + ka;
            mma16(acc[n], a0, a1, a2, a3, bh_[xb], bh_[xb + 4]);
            mma16(acc[n], a0, a1, a2, a3, bl_[xb], bl_[xb + 4]);
        }
    }

    const u32* wh_ = (const u32*)(smem + O_WH);
    const u32* wl_ = (const u32*)(smem + O_WL);
    float* sD = (float*)(smem + O_SD);
    int jw0 = (mt * 16 + gid) * 36, jw1 = (mt * 16 + gid + 8) * 36;
#pragma unroll
    for (int n = 0; n < 4; n++) {
        int rr = nh * 4 + n;
        int qw = ((rr >> 1) << 3) | (tig << 1) | (rr & 1);   // permuted index
        float2 wa = h2f2(wh_[jw0 + qw]), wb = h2f2(wl_[jw0 + qw]);
        float2 wc0 = make_float2(wa.x + wb.x, wa.y + wb.y);
        float2 wa1 = h2f2(wh_[jw1 + qw]), wb1 = h2f2(wl_[jw1 + qw]);
        float2 wc1 = make_float2(wa1.x + wb1.x, wa1.y + wb1.y);
        float dd = acc[n][0] * wc0.x + acc[n][1] * wc0.y
                 + acc[n][2] * wc1.x + acc[n][3] * wc1.y;
#pragma unroll
        for (int o = 16; o; o >>= 1)
            dd += __shfl_xor_sync(0xffffffffu, dd, o);
        if (lane == 0) sD[rr * 10 + mt] = dd;
    }
}

// ---------------------------------------------------------------------------
__device__ __forceinline__ void stage_v(char* smem, int t) {
    const uint4* gv = (const uint4*)g_vh;
    u32* sv = (u32*)(smem + O_V);
    for (int i = t; i < 2560; i += NT) {
        int jd = i >> 4, qd = i & 15;
        uint4 v = __ldcg(gv + jd * 16 + qd);
        *(uint4*)(sv + jd * 68 + qd * 4) = v;
    }
    __syncthreads();
}

// softmax + W' rebuild (c∘W split to fp16 hi/lo, permuted layout)
__device__ __forceinline__ void route_update(char* smem, int t) {
    float* sB = (float*)(smem + O_SB);
    float* sD = (float*)(smem + O_SD);
    float* sC = (float*)(smem + O_SC);
    __syncthreads();                       // sD complete
    if (t < 80) sB[t] += sD[t] * (1.f / 128.f);
    __syncthreads();
    if (t < 80) {
        int r = t / 10;
        float m = -1e30f;
#pragma unroll
        for (int k = 0; k < 10; k++) m = fmaxf(m, sB[r * 10 + k]);
        float den = 0.f;
#pragma unroll
        for (int k = 0; k < 10; k++) den += expf(sB[r * 10 + k] - m);
        sC[t] = expf(sB[t] - m) / den;
    }
    __syncthreads();
    const u32* wh_ = (const u32*)(smem + O_WH);
    const u32* wl_ = (const u32*)(smem + O_WL);
    u32* ph_ = (u32*)(smem + O_PH);
    u32* pl_ = (u32*)(smem + O_PL);
    for (int i = t; i < 5120; i += NT) {   // positions q: jd x 32
        int jd = i >> 5, q = i & 31;
        int r = ((q >> 3) << 1) | (q & 1);  // route of permuted slot q
        float2 a = h2f2(wh_[jd * 36 + q]), b = h2f2(wl_[jd * 36 + q]);
        float c = sC[r * 10 + (jd >> 4)];
        float px = (a.x + b.x) * c, py = (a.y + b.y) * c;
        __half2 ph = __floats2half2_rn(px, py);
        float2 pf = __half22float2(ph);
        __half2 pl = __floats2half2_rn(px - pf.x, py - pf.y);
        ph_[jd * 36 + q] = *(u32*)&ph;
        pl_[jd * 36 + q] = *(u32*)&pl;
    }
    __syncthreads();
}

// ---------------------------------------------------------------------------
__global__ void __launch_bounds__(NT, 1)
caps_kernel(const float* __restrict__ x, const float* __restrict__ W,
            float* __restrict__ out) {
    extern __shared__ char smem[];
    int t = threadIdx.x, blk = blockIdx.x;

    // ---- load + fp16-split W chunk: [r][jd][c] -> halves [jd][perm(rc)] ----
    {
        __half* wh = (__half*)(smem + O_WH);
        __half* wl = (__half*)(smem + O_WL);
        const float* Wg = W + (size_t)blk * 8 * 1280;
        for (int i = t; i < 10240; i += NT) {
            int r = i / 1280, rem = i - r * 1280, jd = rem >> 3, c = rem & 7;
            float v = Wg[i];
            __half h = __float2half_rn(v);
            __half l = __float2half_rn(v - __half2float(h));
            int p = r * 4 + (c >> 1);
            int hp = permq(p) * 2 + (c & 1);
            wh[jd * 72 + hp] = h;
            wl[jd * 72 + hp] = l;
        }
    }
    // ---- load + split x chunk: halves [b][perm(rc)] and XT [rc][b] ----
    {
        __half* xh  = (__half*)(smem + O_XH);
        __half* xl  = (__half*)(smem + O_XL);
        __half* xth = (__half*)(smem + O_XTH);
        __half* xtl = (__half*)(smem + O_XTL);
        for (int i = t; i < 8192; i += NT) {
            int b = i >> 6, rc = i & 63;
            float v = x[(size_t)b * 9216 + blk * 64 + rc];
            __half h = __float2half_rn(v);
            __half l = __float2half_rn(v - __half2float(h));
            int hp = permq(rc >> 1) * 2 + (rc & 1);
            xh[b * 72 + hp] = h;   xl[b * 72 + hp] = l;
            xth[rc * 136 + b] = h; xtl[rc * 136 + b] = l;
        }
    }
    if (t < 80) ((float*)(smem + O_SB))[t] = 0.f;
    __syncthreads();

    // iter 1: c uniform 0.1 folded into store scale
    s_gemm(smem, t, blk, O_WH, O_WL, 0.1f);
    grid_sync(t);
    reduce_squash(smem, blk, t, out, 0);     // v1 -> g_vh
    grid_sync(t);

    // iter 2
    stage_v(smem, t);
    m_delta(smem, t);
    route_update(smem, t);                    // b1, c2, W'
    s_gemm(smem, t, blk, O_PH, O_PL, 1.f);
    grid_sync(t);
    reduce_squash(smem, blk, t, out, 0);     // v2 -> g_vh
    grid_sync(t);

    // iter 3
    stage_v(smem, t);
    m_delta(smem, t);
    route_update(smem, t);                    // b2, c3, W'
    s_gemm(smem, t, blk, O_PH, O_PL, 1.f);
    grid_sync(t);
    reduce_squash(smem, blk, t, out, 1);     // v3 -> out [B,10,16,1]
}

// ---------------------------------------------------------------------------
extern "C" void kernel_launch(void* const* d_in, const int* in_sizes, int n_in,
                              void* d_out, int out_size) {
    const float* x = (const float*)d_in[0];
    const float* W = (const float*)d_in[1];
    if (n_in >= 2 && in_sizes[0] == 1152 * 10 * 16 * 8) {  // inputs swapped
        x = (const float*)d_in[1];
        W = (const float*)d_in[0];
    }
    cudaFuncSetAttribute(caps_kernel,
                         cudaFuncAttributeMaxDynamicSharedMemorySize, SMEM_BYTES);
    caps_kernel<<<GRID, NT, SMEM_BYTES>>>(x, W, (float*)d_out);
}

// round 15
// speedup vs baseline: 1.1615x; 1.1615x over previous
#include <cuda_runtime.h>
#include <cuda_fp16.h>

#define GRID 144
#define NT   640          // 20 warps

typedef unsigned u32;

// ---- global scratch ----
__device__ float g_part[(size_t)GRID * 128 * 160];   // [blk][b][jd] partials
__device__ unsigned short g_vh[160 * 128];           // v fp16 [jd][b]
__device__ unsigned g_cnt = 0;
__device__ unsigned g_gen = 0;

// ---- smem byte offsets ----
#define O_WH  0           // W hi  [160 jd][36 u32(rc pairs, pad)]  23040
#define O_WL  23040       // W lo
#define O_PH  46080       // W' hi (c*W)
#define O_PL  69120       // W' lo
#define O_XH  92160       // X hi  [128 b][36 u32]
#define O_XL  110592      // X lo
#define O_XTH 129024      // XT hi [64 rc][136 halves(b)]
#define O_XTL 146432      // XT lo
#define O_V   163840      // V fp16 [160 jd][68 u32(b pairs)]
#define O_SB  207360      // float[80] b_ij
#define O_SD  207680      // float[80] delta
#define O_SC  208000      // float[80] c
#define O_SRD 208320      // float[2304] reduce scratch
#define SMEM_BYTES 217536

// ---- fp16 mma m16n8k16, D += A*B ----
__device__ __forceinline__ void mma16(float* c, u32 a0, u32 a1, u32 a2, u32 a3,
                                      u32 b0, u32 b1) {
    asm volatile(
        "mma.sync.aligned.m16n8k16.row.col.f32.f16.f16.f32 "
        "{%0,%1,%2,%3},{%4,%5,%6,%7},{%8,%9},{%0,%1,%2,%3};"
        : "+f"(c[0]), "+f"(c[1]), "+f"(c[2]), "+f"(c[3])
        : "r"(a0), "r"(a1), "r"(a2), "r"(a3), "r"(b0), "r"(b1));
}
__device__ __forceinline__ float2 h2f2(u32 h) {
    return __half22float2(*(const __half2*)&h);
}

// ---- one-wave grid barrier (ldcg poll) ----
__device__ __forceinline__ void grid_sync(int t) {
    __syncthreads();
    if (t == 0) {
        __threadfence();
        unsigned gen = __ldcg(&g_gen);
        if (atomicAdd(&g_cnt, 1u) == GRID - 1) {
            atomicExch(&g_cnt, 0u);
            __threadfence();
            __stcg(&g_gen, gen + 1);
        } else {
            while (__ldcg(&g_gen) == gen) { __nanosleep(32); }
        }
        __threadfence();
    }
    __syncthreads();
}

// ---------------------------------------------------------------------------
// s-GEMM (R9 structure): partial s[b,jd] = scale * sum_rc X[b,rc]*A[jd,rc]
// 20 warps: warp = (mt in [0,10) jd-tile of 16, nh in {0,1} b-half of 64)
// per warp: 8 n-tiles x 4 kt x 3 split = 96 MMAs. Stores scalar to [b][jd].
// ---------------------------------------------------------------------------
__device__ __forceinline__ void s_gemm(char* smem, int t, int blk,
                                       int AH, int AL, float scale) {
    int lane = t & 31, w = t >> 5, gid = lane >> 2, tig = lane & 3;
    int mt = w % 10, nh = w / 10;
    const u32* xh_ = (const u32*)(smem + O_XH);
    const u32* xl_ = (const u32*)(smem + O_XL);
    const u32* ah_ = (const u32*)(smem + AH);
    const u32* al_ = (const u32*)(smem + AL);
    int jr0 = (mt * 16 + gid) * 36, jr1 = (mt * 16 + gid + 8) * 36;

    float acc[8][4];
#pragma unroll
    for (int n = 0; n < 8; n++)
#pragma unroll
        for (int k = 0; k < 4; k++) acc[n][k] = 0.f;

#pragma unroll
    for (int kt = 0; kt < 4; kt++) {
        int ka = kt * 8 + tig;
        u32 ah0 = ah_[jr0 + ka], ah1 = ah_[jr1 + ka];
        u32 ah2 = ah_[jr0 + ka + 4], ah3 = ah_[jr1 + ka + 4];
        u32 al0 = al_[jr0 + ka], al1 = al_[jr1 + ka];
        u32 al2 = al_[jr0 + ka + 4], al3 = al_[jr1 + ka + 4];
#pragma unroll
        for (int n = 0; n < 8; n++) {
            int xb = ((nh * 8 + n) * 8 + gid) * 36 + ka;
            u32 bh0 = xh_[xb], bh1 = xh_[xb + 4];
            u32 bl0 = xl_[xb], bl1 = xl_[xb + 4];
            mma16(acc[n], ah0, ah1, ah2, ah3, bh0, bh1);
            mma16(acc[n], ah0, ah1, ah2, ah3, bl0, bl1);
            mma16(acc[n], al0, al1, al2, al3, bh0, bh1);
        }
    }

    // fragment: rows = jd (mt*16+gid, +8), cols = b ((nh*8+n)*8 + 2*tig, +1)
    float* gp = g_part + (size_t)blk * 20480;
    int jd0 = mt * 16 + gid;
#pragma unroll
    for (int n = 0; n < 8; n++) {
        int bc = (nh * 8 + n) * 8 + 2 * tig;
        __stcg(gp + (size_t)bc * 160 + jd0,             acc[n][0] * scale);
        __stcg(gp + (size_t)(bc + 1) * 160 + jd0,       acc[n][1] * scale);
        __stcg(gp + (size_t)bc * 160 + jd0 + 8,         acc[n][2] * scale);
        __stcg(gp + (size_t)(bc + 1) * 160 + jd0 + 8,   acc[n][3] * scale);
    }
}

// ---------------------------------------------------------------------------
// merged reduce + squash: all 144 blocks, 9 (j,b) columns each.
// stage1: 576 threads = ci(9) x q(4 d-quads) x ks(16 k-split); 9 float4 loads
// stage2: 160 threads (ci,d): sum 16 k-splits, squash over d (shfl w16)
// ---------------------------------------------------------------------------
__device__ __forceinline__ void reduce_squash(char* smem, int blk, int t,
                                              float* out, int fin) {
    float*  SRD  = (float*)(smem + O_SRD);
    float4* SRD4 = (float4*)SRD;
    if (t < 576) {
        int ci = t >> 6, q = (t >> 4) & 3, ks = t & 15;
        int col = blk * 9 + ci;
        int colc = col < 1280 ? col : 1279;
        int j = colc >> 7, b = colc & 127;
        const size_t BS = 5120;   // float4 per partial block
        const float4* p = (const float4*)
            (g_part + (size_t)ks * 20480 + (size_t)b * 160 + j * 16 + q * 4);
        float4 a0 = __ldcg(p);
        float4 a1 = __ldcg(p + 16 * BS);
        float4 a2 = __ldcg(p + 32 * BS);
        float4 a3 = __ldcg(p + 48 * BS);
        float4 v0 = __ldcg(p + 64 * BS);
        float4 v1 = __ldcg(p + 80 * BS);
        float4 v2 = __ldcg(p + 96 * BS);
        float4 v3 = __ldcg(p + 112 * BS);
        float4 v4 = __ldcg(p + 128 * BS);
        a0.x += v0.x; a0.y += v0.y; a0.z += v0.z; a0.w += v0.w;
        a1.x += v1.x; a1.y += v1.y; a1.z += v1.z; a1.w += v1.w;
        a2.x += v2.x; a2.y += v2.y; a2.z += v2.z; a2.w += v2.w;
        a3.x += v3.x; a3.y += v3.y; a3.z += v3.z; a3.w += v3.w;
        a0.x += v4.x; a0.y += v4.y; a0.z += v4.z; a0.w += v4.w;
        a0.x += a1.x + a2.x + a3.x;
        a0.y += a1.y + a2.y + a3.y;
        a0.z += a1.z + a2.z + a3.z;
        a0.w += a1.w + a2.w + a3.w;
        SRD4[ci * 64 + q * 16 + ks] = a0;
    }
    __syncthreads();
    if (t < 160) {
        int ci = t >> 4, d = t & 15;
        int cir = ci < 9 ? ci : 8;
        int col = blk * 9 + ci;
        int valid = (ci < 9) && (col < 1280);
        int colc = col < 1280 ? col : 1279;
        int j = colc >> 7, b = colc & 127;
        float s = 0.f;
#pragma unroll
        for (int ks = 0; ks < 16; ks++)
            s += SRD[cir * 256 + (d >> 2) * 64 + ks * 4 + (d & 3)];
        float sq = s * s;
#pragma unroll
        for (int o = 8; o; o >>= 1) sq += __shfl_xor_sync(0xffffffffu, sq, o, 16);
        float v = s * (sqrtf(sq) / (1.f + sq));
        if (valid) {
            if (fin) out[b * 160 + j * 16 + d] = v;
            else g_vh[(j * 16 + d) * 128 + b] = __half_as_ushort(__float2half_rn(v));
        }
    }
}

// ---------------------------------------------------------------------------
// M-GEMM + delta: M[jd,rc] = sum_b V[jd,b]*X[rc,b];
// delta[r,j=mt] = sum_{d,c} W[jd,rc]*M[jd,rc]; warp = (mt, nh): 4 routes each
// ---------------------------------------------------------------------------
__device__ __forceinline__ void m_delta(char* smem, int t) {
    int lane = t & 31, w = t >> 5, gid = lane >> 2, tig = lane & 3;
    int mt = w % 10, nh = w / 10;
    const u32* v_  = (const u32*)(smem + O_V);
    const u32* bh_ = (const u32*)(smem + O_XTH);
    const u32* bl_ = (const u32*)(smem + O_XTL);
    int jr0 = (mt * 16 + gid) * 68, jr1 = (mt * 16 + gid + 8) * 68;

    float acc[4][4];
#pragma unroll
    for (int n = 0; n < 4; n++)
#pragma unroll
        for (int k = 0; k < 4; k++) acc[n][k] = 0.f;

#pragma unroll
    for (int kt = 0; kt < 8; kt++) {
        int ka = kt * 8 + tig;
        u32 a0 = v_[jr0 + ka], a1 = v_[jr1 + ka];
        u32 a2 = v_[jr0 + ka + 4], a3 = v_[jr1 + ka + 4];
#pragma unroll
        for (int n = 0; n < 4; n++) {
            int xb = ((nh * 4 + n) * 8 + gid) * 68 + ka;
            mma16(acc[n], a0, a1, a2, a3, bh_[xb], bh_[xb + 4]);
            mma16(acc[n], a0, a1, a2, a3, bl_[xb], bl_[xb + 4]);
        }
    }

    const u32* wh_ = (const u32*)(smem + O_WH);
    const u32* wl_ = (const u32*)(smem + O_WL);
    float* sD = (float*)(smem + O_SD);
    int jw0 = (mt * 16 + gid) * 36, jw1 = (mt * 16 + gid + 8) * 36;
#pragma unroll
    for (int n = 0; n < 4; n++) {
        int rr = nh * 4 + n;
        int wc = rr * 4 + tig;
        float2 wa = h2f2(wh_[jw0 + wc]), wb = h2f2(wl_[jw0 + wc]);
        float2 wc0 = make_float2(wa.x + wb.x, wa.y + wb.y);
        float2 wa1 = h2f2(wh_[jw1 + wc]), wb1 = h2f2(wl_[jw1 + wc]);
        float2 wc1 = make_float2(wa1.x + wb1.x, wa1.y + wb1.y);
        float dd = acc[n][0] * wc0.x + acc[n][1] * wc0.y
                 + acc[n][2] * wc1.x + acc[n][3] * wc1.y;
#pragma unroll
        for (int o = 16; o; o >>= 1)
            dd += __shfl_xor_sync(0xffffffffu, dd, o);
        if (lane == 0) sD[rr * 10 + mt] = dd;
    }
}

// ---------------------------------------------------------------------------
__device__ __forceinline__ void stage_v(char* smem, int t) {
    const uint4* gv = (const uint4*)g_vh;
    u32* sv = (u32*)(smem + O_V);
    for (int i = t; i < 2560; i += NT) {
        int jd = i >> 4, qd = i & 15;
        uint4 v = __ldcg(gv + jd * 16 + qd);
        *(uint4*)(sv + jd * 68 + qd * 4) = v;
    }
    __syncthreads();
}

// softmax + W' rebuild (c∘W split to fp16 hi/lo)
__device__ __forceinline__ void route_update(char* smem, int t) {
    float* sB = (float*)(smem + O_SB);
    float* sD = (float*)(smem + O_SD);
    float* sC = (float*)(smem + O_SC);
    __syncthreads();                       // sD complete
    if (t < 80) sB[t] += sD[t] * (1.f / 128.f);
    __syncthreads();
    if (t < 80) {
        int r = t / 10;
        float m = -1e30f;
#pragma unroll
        for (int k = 0; k < 10; k++) m = fmaxf(m, sB[r * 10 + k]);
        float den = 0.f;
#pragma unroll
        for (int k = 0; k < 10; k++) den += expf(sB[r * 10 + k] - m);
        sC[t] = expf(sB[t] - m) / den;
    }
    __syncthreads();
    const u32* wh_ = (const u32*)(smem + O_WH);
    const u32* wl_ = (const u32*)(smem + O_WL);
    u32* ph_ = (u32*)(smem + O_PH);
    u32* pl_ = (u32*)(smem + O_PL);
    for (int i = t; i < 5120; i += NT) {   // u32 pairs: jd x 32
        int jd = i >> 5, rcu = i & 31;
        float2 a = h2f2(wh_[jd * 36 + rcu]), b = h2f2(wl_[jd * 36 + rcu]);
        float c = sC[(rcu >> 2) * 10 + (jd >> 4)];
        float px = (a.x + b.x) * c, py = (a.y + b.y) * c;
        __half2 ph = __floats2half2_rn(px, py);
        float2 pf = __half22float2(ph);
        __half2 pl = __floats2half2_rn(px - pf.x, py - pf.y);
        ph_[jd * 36 + rcu] = *(u32*)&ph;
        pl_[jd * 36 + rcu] = *(u32*)&pl;
    }
    __syncthreads();
}

// ---------------------------------------------------------------------------
__global__ void __launch_bounds__(NT, 1)
caps_kernel(const float* __restrict__ x, const float* __restrict__ W,
            float* __restrict__ out) {
    extern __shared__ char smem[];
    int t = threadIdx.x, blk = blockIdx.x;

    // ---- load + fp16-split W chunk: [r][jd][c] -> halves [jd][rc] ----
    {
        __half* wh = (__half*)(smem + O_WH);
        __half* wl = (__half*)(smem + O_WL);
        const float* Wg = W + (size_t)blk * 8 * 1280;
        for (int i = t; i < 10240; i += NT) {
            int r = i / 1280, rem = i - r * 1280, jd = rem >> 3, c = rem & 7;
            float v = Wg[i];
            __half h = __float2half_rn(v);
            __half l = __float2half_rn(v - __half2float(h));
            wh[jd * 72 + r * 8 + c] = h;
            wl[jd * 72 + r * 8 + c] = l;
        }
    }
    // ---- load + split x chunk: halves [b][rc] and [rc][b] ----
    {
        __half* xh  = (__half*)(smem + O_XH);
        __half* xl  = (__half*)(smem + O_XL);
        __half* xth = (__half*)(smem + O_XTH);
        __half* xtl = (__half*)(smem + O_XTL);
        for (int i = t; i < 8192; i += NT) {
            int b = i >> 6, rc = i & 63;
            float v = x[(size_t)b * 9216 + blk * 64 + rc];
            __half h = __float2half_rn(v);
            __half l = __float2half_rn(v - __half2float(h));
            xh[b * 72 + rc] = h;   xl[b * 72 + rc] = l;
            xth[rc * 136 + b] = h; xtl[rc * 136 + b] = l;
        }
    }
    if (t < 80) ((float*)(smem + O_SB))[t] = 0.f;
    __syncthreads();

    // iter 1: c uniform 0.1 folded into store scale
    s_gemm(smem, t, blk, O_WH, O_WL, 0.1f);
    grid_sync(t);
    reduce_squash(smem, blk, t, out, 0);     // v1 -> g_vh
    grid_sync(t);

    // iter 2
    stage_v(smem, t);
    m_delta(smem, t);
    route_update(smem, t);                    // b1, c2, W'
    s_gemm(smem, t, blk, O_PH, O_PL, 1.f);
    grid_sync(t);
    reduce_squash(smem, blk, t, out, 0);     // v2 -> g_vh
    grid_sync(t);

    // iter 3
    stage_v(smem, t);
    m_delta(smem, t);
    route_update(smem, t);                    // b2, c3, W'
    s_gemm(smem, t, blk, O_PH, O_PL, 1.f);
    grid_sync(t);
    reduce_squash(smem, blk, t, out, 1);     // v3 -> out [B,10,16,1]
}

// ---------------------------------------------------------------------------
extern "C" void kernel_launch(void* const* d_in, const int* in_sizes, int n_in,
                              void* d_out, int out_size) {
    const float* x = (const float*)d_in[0];
    const float* W = (const float*)d_in[1];
    if (n_in >= 2 && in_sizes[0] == 1152 * 10 * 16 * 8) {  // inputs swapped
        x = (const float*)d_in[1];
        W = (const float*)d_in[0];
    }
    cudaFuncSetAttribute(caps_kernel,
                         cudaFuncAttributeMaxDynamicSharedMemorySize, SMEM_BYTES);
    caps_kernel<<<GRID, NT, SMEM_BYTES>>>(x, W, (float*)d_out);
}